// round 1
// baseline (speedup 1.0000x reference)
#include <cuda_runtime.h>
#include <cuda_bf16.h>

#define HH 128
#define WW 128
#define CC 64
#define OO 64
#define BB 4
#define K2V 9
#define HWsz (HH*WW)

// Scratch (no cudaMalloc allowed)
__device__ __align__(16) float g_om[BB*27*HWsz];     // offset-conv output (B,27,H,W)
__device__ __align__(16) float g_wt[K2V*CC*OO];      // main weight transposed [k][c][o]
__device__ __align__(16) float g_womt[K2V*CC*32];    // offset weight transposed+padded [k][c][32]

// ---------------------------------------------------------------------------
// Kernel 0: transpose weights into [k][c][o] layouts for broadcast-friendly LDS
// ---------------------------------------------------------------------------
__global__ void prep_weights(const float* __restrict__ weight,
                             const float* __restrict__ w_om) {
    int i = blockIdx.x * 256 + threadIdx.x;
    if (i < K2V*CC*OO) {
        int o = i % OO;
        int c = (i / OO) % CC;
        int k = i / (OO*CC);
        g_wt[i] = weight[(o*CC + c)*K2V + k];
    }
    if (i < K2V*CC*32) {
        int o = i % 32;
        int c = (i / 32) % CC;
        int k = i / (32*CC);
        g_womt[i] = (o < 27) ? w_om[(o*CC + c)*K2V + k] : 0.f;
    }
}

// ---------------------------------------------------------------------------
// Kernel 1: offset conv  om = conv3x3(x, w_om) + b_om   (27 out ch, pad 1)
// Block: 256 threads, one image row (128 px). Tile: 128px x 32oc(padded).
// Thread: 4 pixels (stride 32) x 4 out-ch -> 16 accumulators.
// ---------------------------------------------------------------------------
__global__ __launch_bounds__(256, 3)
void offset_conv(const float* __restrict__ x, const float* __restrict__ b_om) {
    __shared__ __align__(16) float vals_s[CC*WW];   // 32 KB
    __shared__ __align__(16) float w_s[CC*32];      // 8 KB

    const int t    = threadIdx.x;
    const int b    = blockIdx.x >> 7;
    const int y    = blockIdx.x & 127;
    const int p    = t & 127;       // pixel (w) in gather phase
    const int half = t >> 7;        // channel half in gather phase
    const int pp   = t & 31;        // pixel lane in compute phase
    const int og   = t >> 5;        // out-ch group (0..7), o = og*4..og*4+3

    float acc[4][4];
    #pragma unroll
    for (int j = 0; j < 4; j++)
        #pragma unroll
        for (int o = 0; o < 4; o++) acc[j][o] = 0.f;

    const float* xb = x + (size_t)(b*CC + half*32) * HWsz;

    for (int k = 0; k < K2V; k++) {
        const int ky = k / 3 - 1;
        const int kx = k % 3 - 1;
        const int yy = y + ky;
        const int xx = p + kx;
        const bool inb = (yy >= 0) & (yy < HH) & (xx >= 0) & (xx < WW);
        // ---- gather shifted x into smem: thread does 32 channels of its pixel
        #pragma unroll 8
        for (int ci = 0; ci < 32; ci++) {
            float v = 0.f;
            if (inb) v = xb[ci*HWsz + yy*WW + xx];
            vals_s[(half*32 + ci)*WW + p] = v;
        }
        // ---- stage this tap's weights: 64*32 floats = 512 float4
        {
            const float4* wsrc = (const float4*)(g_womt + k*CC*32);
            float4* wdst = (float4*)w_s;
            wdst[t]       = wsrc[t];
            wdst[t + 256] = wsrc[t + 256];
        }
        __syncthreads();
        // ---- accumulate
        #pragma unroll 8
        for (int c = 0; c < CC; c++) {
            float v0 = vals_s[c*WW + pp];
            float v1 = vals_s[c*WW + pp + 32];
            float v2 = vals_s[c*WW + pp + 64];
            float v3 = vals_s[c*WW + pp + 96];
            float4 w4 = *(const float4*)(w_s + c*32 + og*4);
            acc[0][0] += v0*w4.x; acc[0][1] += v0*w4.y; acc[0][2] += v0*w4.z; acc[0][3] += v0*w4.w;
            acc[1][0] += v1*w4.x; acc[1][1] += v1*w4.y; acc[1][2] += v1*w4.z; acc[1][3] += v1*w4.w;
            acc[2][0] += v2*w4.x; acc[2][1] += v2*w4.y; acc[2][2] += v2*w4.z; acc[2][3] += v2*w4.w;
            acc[3][0] += v3*w4.x; acc[3][1] += v3*w4.y; acc[3][2] += v3*w4.z; acc[3][3] += v3*w4.w;
        }
        __syncthreads();
    }
    // ---- write om (+bias), only the real 27 channels
    #pragma unroll
    for (int oi = 0; oi < 4; oi++) {
        int o = og*4 + oi;
        if (o < 27) {
            float bv = b_om[o];
            float* ob = g_om + (size_t)((b*27 + o)*HH + y) * WW;
            #pragma unroll
            for (int j = 0; j < 4; j++)
                ob[pp + 32*j] = acc[j][oi] + bv;
        }
    }
}

// ---------------------------------------------------------------------------
// Kernel 2: fused deformable conv.
// Block: 256 threads, one image row. Per tap: bilinear gather -> smem vals,
// then tile 128px x 64oc, thread = 4 pixels (stride 32) x 8 oc = 32 accs.
// Validity + mask folded into the 4 corner weights -> branch-free gathers.
// ---------------------------------------------------------------------------
__global__ __launch_bounds__(256, 2)
void deform_conv(const float* __restrict__ x,
                 const float* __restrict__ bias,
                 float* __restrict__ out) {
    extern __shared__ __align__(16) float sm[];
    float* vals_s = sm;                       // 64*128
    float* w_s    = vals_s + CC*WW;           // 64*64
    float* ys_s   = w_s + CC*OO;              // 9*128
    float* xs_s   = ys_s + K2V*WW;            // 9*128
    float* ms_s   = xs_s + K2V*WW;            // 9*128

    const int t    = threadIdx.x;
    const int b    = blockIdx.x >> 7;
    const int y    = blockIdx.x & 127;
    const int p    = t & 127;
    const int half = t >> 7;
    const int pp   = t & 31;
    const int og   = t >> 5;                  // o = og*8 .. og*8+7

    // ---- phase 0: sampling positions + mask for all 9 taps of this row
    {
        const float* omb = g_om + (size_t)b*27*HWsz + y*WW + p;
        for (int k = half; k < K2V; k += 2) {
            float dy = omb[(size_t)(2*k)   * HWsz];
            float dx = omb[(size_t)(2*k+1) * HWsz];
            float mv = omb[(size_t)(18+k)  * HWsz];
            ys_s[k*WW + p] = dy + (float)(y + k/3 - 1);
            xs_s[k*WW + p] = dx + (float)(p + k%3 - 1);
            ms_s[k*WW + p] = 1.f / (1.f + __expf(-mv));
        }
    }

    float acc[4][8];
    #pragma unroll
    for (int j = 0; j < 4; j++)
        #pragma unroll
        for (int o = 0; o < 8; o++) acc[j][o] = 0.f;

    const float* xb = x + (size_t)(b*CC + half*32) * HWsz;
    __syncthreads();

    for (int k = 0; k < K2V; k++) {
        // ---- bilinear gather: thread handles its pixel for 32 channels
        {
            float ys = ys_s[k*WW + p];
            float xs = xs_s[k*WW + p];
            float m  = ms_s[k*WW + p];
            float y0f = floorf(ys), x0f = floorf(xs);
            float wy1 = ys - y0f, wx1 = xs - x0f;
            float wy0 = 1.f - wy1, wx0 = 1.f - wx1;
            int y0 = (int)y0f, x0 = (int)x0f;
            int y1 = y0 + 1,   x1 = x0 + 1;
            float vy0 = (y0 >= 0 && y0 < HH) ? 1.f : 0.f;
            float vy1 = (y1 >= 0 && y1 < HH) ? 1.f : 0.f;
            float vx0 = (x0 >= 0 && x0 < WW) ? 1.f : 0.f;
            float vx1 = (x1 >= 0 && x1 < WW) ? 1.f : 0.f;
            float w00 = wy0*wx0*vy0*vx0*m;
            float w01 = wy0*wx1*vy0*vx1*m;
            float w10 = wy1*wx0*vy1*vx0*m;
            float w11 = wy1*wx1*vy1*vx1*m;
            int y0c = min(max(y0, 0), HH-1), y1c = min(max(y1, 0), HH-1);
            int x0c = min(max(x0, 0), WW-1), x1c = min(max(x1, 0), WW-1);
            int o00 = y0c*WW + x0c, o01 = y0c*WW + x1c;
            int o10 = y1c*WW + x0c, o11 = y1c*WW + x1c;
            #pragma unroll 8
            for (int ci = 0; ci < 32; ci++) {
                const float* xc = xb + ci*HWsz;
                vals_s[(half*32 + ci)*WW + p] =
                    xc[o00]*w00 + xc[o01]*w01 + xc[o10]*w10 + xc[o11]*w11;
            }
        }
        // ---- stage this tap's weights: 64*64 floats = 1024 float4
        {
            const float4* wsrc = (const float4*)(g_wt + k*CC*OO);
            float4* wdst = (float4*)w_s;
            #pragma unroll
            for (int r = 0; r < 4; r++) wdst[t + 256*r] = wsrc[t + 256*r];
        }
        __syncthreads();
        // ---- accumulate: 4px x 8oc register tile
        #pragma unroll 4
        for (int c = 0; c < CC; c++) {
            float v0 = vals_s[c*WW + pp];
            float v1 = vals_s[c*WW + pp + 32];
            float v2 = vals_s[c*WW + pp + 64];
            float v3 = vals_s[c*WW + pp + 96];
            float4 wa = *(const float4*)(w_s + c*OO + og*8);
            float4 wb = *(const float4*)(w_s + c*OO + og*8 + 4);
            acc[0][0]+=v0*wa.x; acc[0][1]+=v0*wa.y; acc[0][2]+=v0*wa.z; acc[0][3]+=v0*wa.w;
            acc[0][4]+=v0*wb.x; acc[0][5]+=v0*wb.y; acc[0][6]+=v0*wb.z; acc[0][7]+=v0*wb.w;
            acc[1][0]+=v1*wa.x; acc[1][1]+=v1*wa.y; acc[1][2]+=v1*wa.z; acc[1][3]+=v1*wa.w;
            acc[1][4]+=v1*wb.x; acc[1][5]+=v1*wb.y; acc[1][6]+=v1*wb.z; acc[1][7]+=v1*wb.w;
            acc[2][0]+=v2*wa.x; acc[2][1]+=v2*wa.y; acc[2][2]+=v2*wa.z; acc[2][3]+=v2*wa.w;
            acc[2][4]+=v2*wb.x; acc[2][5]+=v2*wb.y; acc[2][6]+=v2*wb.z; acc[2][7]+=v2*wb.w;
            acc[3][0]+=v3*wa.x; acc[3][1]+=v3*wa.y; acc[3][2]+=v3*wa.z; acc[3][3]+=v3*wa.w;
            acc[3][4]+=v3*wb.x; acc[3][5]+=v3*wb.y; acc[3][6]+=v3*wb.z; acc[3][7]+=v3*wb.w;
        }
        __syncthreads();
    }
    // ---- epilogue: add bias, write out (fully covers the poisoned buffer)
    #pragma unroll
    for (int oi = 0; oi < 8; oi++) {
        int o = og*8 + oi;
        float bv = bias[o];
        float* ob = out + (size_t)((b*OO + o)*HH + y) * WW;
        #pragma unroll
        for (int j = 0; j < 4; j++)
            ob[pp + 32*j] = acc[j][oi] + bv;
    }
}

// ---------------------------------------------------------------------------
extern "C" void kernel_launch(void* const* d_in, const int* in_sizes, int n_in,
                              void* d_out, int out_size) {
    const float* x      = (const float*)d_in[0];  // (4,64,128,128)
    const float* w_om   = (const float*)d_in[1];  // (27,64,3,3)
    const float* b_om   = (const float*)d_in[2];  // (27,)
    const float* weight = (const float*)d_in[3];  // (64,64,3,3)
    const float* bias   = (const float*)d_in[4];  // (64,)
    float* out = (float*)d_out;                   // (4,64,128,128)

    (void)in_sizes; (void)n_in; (void)out_size;

    static const int smem_bytes = (CC*WW + CC*OO + 3*K2V*WW) * (int)sizeof(float); // 62976
    cudaFuncSetAttribute(deform_conv, cudaFuncAttributeMaxDynamicSharedMemorySize, smem_bytes);

    prep_weights<<<(K2V*CC*OO + 255)/256, 256>>>(weight, w_om);
    offset_conv<<<BB*HH, 256>>>(x, b_om);
    deform_conv<<<BB*HH, 256, smem_bytes>>>(x, bias, out);
}

// round 17
// speedup vs baseline: 1.0671x; 1.0671x over previous
#include <cuda_runtime.h>
#include <cuda_bf16.h>

#define HH 128
#define WW 128
#define CC 64
#define OO 64
#define BB 4
#define K2V 9
#define HWsz (HH*WW)

typedef unsigned long long u64;

// packed f32x2 helpers (sm_103a; FFMA2 only reachable via PTX)
__device__ __forceinline__ u64 pk2(float a, float b) {
    u64 r; asm("mov.b64 %0,{%1,%2};" : "=l"(r) : "f"(a), "f"(b)); return r;
}
__device__ __forceinline__ void ffma2(u64& d, u64 a, u64 b) {
    asm("fma.rn.f32x2 %0,%1,%2,%0;" : "+l"(d) : "l"(a), "l"(b));
}
__device__ __forceinline__ float2 upk2(u64 v) {
    float2 r; asm("mov.b64 {%0,%1},%2;" : "=f"(r.x), "=f"(r.y) : "l"(v)); return r;
}

// Scratch (no cudaMalloc allowed)
__device__ __align__(16) float g_om[BB*27*HWsz];     // offset-conv output (B,27,H,W)
__device__ __align__(16) float g_wt[K2V*CC*OO];      // main weight transposed [k][c][o]
__device__ __align__(16) float g_womt[K2V*CC*32];    // offset weight transposed+padded [k][c][32]

// ---------------------------------------------------------------------------
// Kernel 0: transpose weights into [k][c][o] layouts for broadcast-friendly LDS
// ---------------------------------------------------------------------------
__global__ void prep_weights(const float* __restrict__ weight,
                             const float* __restrict__ w_om) {
    int i = blockIdx.x * 256 + threadIdx.x;
    if (i < K2V*CC*OO) {
        int o = i % OO;
        int c = (i / OO) % CC;
        int k = i / (OO*CC);
        g_wt[i] = weight[(o*CC + c)*K2V + k];
    }
    if (i < K2V*CC*32) {
        int o = i % 32;
        int c = (i / 32) % CC;
        int k = i / (32*CC);
        g_womt[i] = (o < 27) ? w_om[(o*CC + c)*K2V + k] : 0.f;
    }
}

// ---------------------------------------------------------------------------
// Kernel 1: offset conv  om = conv3x3(x, w_om) + b_om   (27 out ch, pad 1)
// Block: 256 threads, one image row. Tile 128px x 32oc(padded).
// Thread: 4 pixels (stride 32) x 2 oc-pairs (f32x2) = 8 packed accumulators.
// ---------------------------------------------------------------------------
__global__ __launch_bounds__(256, 3)
void offset_conv(const float* __restrict__ x, const float* __restrict__ b_om) {
    __shared__ __align__(16) float vals_s[CC*WW];   // 32 KB
    __shared__ __align__(16) float w_s[CC*32];      // 8 KB

    const int t    = threadIdx.x;
    const int b    = blockIdx.x >> 7;
    const int y    = blockIdx.x & 127;
    const int p    = t & 127;       // pixel (w) in gather phase
    const int half = t >> 7;        // channel half in gather phase
    const int pp   = t & 31;        // pixel lane in compute phase
    const int og   = t >> 5;        // out-ch group (0..7), o = og*4..og*4+3

    u64 acc[4][2];
    #pragma unroll
    for (int j = 0; j < 4; j++) { acc[j][0] = 0ull; acc[j][1] = 0ull; }

    const float* xb = x + (size_t)(b*CC + half*32) * HWsz;

    for (int k = 0; k < K2V; k++) {
        const int ky = k / 3 - 1;
        const int kx = k % 3 - 1;
        const int yy = y + ky;
        const int xx = p + kx;
        const bool inb = (yy >= 0) & (yy < HH) & (xx >= 0) & (xx < WW);
        // ---- gather shifted x into smem: thread does 32 channels of its pixel
        #pragma unroll 8
        for (int ci = 0; ci < 32; ci++) {
            float v = 0.f;
            if (inb) v = xb[ci*HWsz + yy*WW + xx];
            vals_s[(half*32 + ci)*WW + p] = v;
        }
        // ---- stage this tap's weights: 64*32 floats = 512 float4
        {
            const float4* wsrc = (const float4*)(g_womt + k*CC*32);
            float4* wdst = (float4*)w_s;
            wdst[t]       = wsrc[t];
            wdst[t + 256] = wsrc[t + 256];
        }
        __syncthreads();
        // ---- accumulate (packed over oc pairs)
        #pragma unroll 8
        for (int c = 0; c < CC; c++) {
            u64 v0 = pk2(vals_s[c*WW + pp],      vals_s[c*WW + pp]);
            u64 v1 = pk2(vals_s[c*WW + pp + 32], vals_s[c*WW + pp + 32]);
            u64 v2 = pk2(vals_s[c*WW + pp + 64], vals_s[c*WW + pp + 64]);
            u64 v3 = pk2(vals_s[c*WW + pp + 96], vals_s[c*WW + pp + 96]);
            const u64* wp = (const u64*)(w_s + c*32 + og*4);
            u64 wA = wp[0], wB = wp[1];
            ffma2(acc[0][0], v0, wA); ffma2(acc[0][1], v0, wB);
            ffma2(acc[1][0], v1, wA); ffma2(acc[1][1], v1, wB);
            ffma2(acc[2][0], v2, wA); ffma2(acc[2][1], v2, wB);
            ffma2(acc[3][0], v3, wA); ffma2(acc[3][1], v3, wB);
        }
        __syncthreads();
    }
    // ---- write om (+bias), only the real 27 channels
    #pragma unroll
    for (int op = 0; op < 2; op++) {
        #pragma unroll
        for (int sub = 0; sub < 2; sub++) {
            int o = og*4 + op*2 + sub;
            if (o < 27) {
                float bv = b_om[o];
                float* ob = g_om + (size_t)((b*27 + o)*HH + y) * WW;
                #pragma unroll
                for (int j = 0; j < 4; j++) {
                    float2 a = upk2(acc[j][op]);
                    ob[pp + 32*j] = (sub ? a.y : a.x) + bv;
                }
            }
        }
    }
}

// ---------------------------------------------------------------------------
// Kernel 2: fused deformable conv.
// Block: 256 threads, one image row. Per tap: bilinear gather -> smem vals,
// then tile 128px x 64oc, thread = 4 pixels x 4 oc-pairs (f32x2) = 16 packed accs.
// Validity + mask folded into the 4 corner weights -> branch-free gathers.
// ---------------------------------------------------------------------------
__global__ __launch_bounds__(256, 2)
void deform_conv(const float* __restrict__ x,
                 const float* __restrict__ bias,
                 float* __restrict__ out) {
    extern __shared__ __align__(16) float sm[];
    float* vals_s = sm;                       // 64*128
    float* w_s    = vals_s + CC*WW;           // 64*64
    float* ys_s   = w_s + CC*OO;              // 9*128
    float* xs_s   = ys_s + K2V*WW;            // 9*128
    float* ms_s   = xs_s + K2V*WW;            // 9*128

    const int t    = threadIdx.x;
    const int b    = blockIdx.x >> 7;
    const int y    = blockIdx.x & 127;
    const int p    = t & 127;
    const int half = t >> 7;
    const int pp   = t & 31;
    const int og   = t >> 5;                  // o = og*8 .. og*8+7

    // ---- phase 0: sampling positions + mask for all 9 taps of this row
    {
        const float* omb = g_om + (size_t)b*27*HWsz + y*WW + p;
        for (int k = half; k < K2V; k += 2) {
            float dy = omb[(size_t)(2*k)   * HWsz];
            float dx = omb[(size_t)(2*k+1) * HWsz];
            float mv = omb[(size_t)(18+k)  * HWsz];
            ys_s[k*WW + p] = dy + (float)(y + k/3 - 1);
            xs_s[k*WW + p] = dx + (float)(p + k%3 - 1);
            ms_s[k*WW + p] = 1.f / (1.f + __expf(-mv));
        }
    }

    u64 acc[4][4];
    #pragma unroll
    for (int j = 0; j < 4; j++)
        #pragma unroll
        for (int o = 0; o < 4; o++) acc[j][o] = 0ull;

    const float* xb = x + (size_t)(b*CC + half*32) * HWsz;
    __syncthreads();

    for (int k = 0; k < K2V; k++) {
        // ---- bilinear gather: thread handles its pixel for 32 channels
        {
            float ys = ys_s[k*WW + p];
            float xs = xs_s[k*WW + p];
            float m  = ms_s[k*WW + p];
            float y0f = floorf(ys), x0f = floorf(xs);
            float wy1 = ys - y0f, wx1 = xs - x0f;
            float wy0 = 1.f - wy1, wx0 = 1.f - wx1;
            int y0 = (int)y0f, x0 = (int)x0f;
            int y1 = y0 + 1,   x1 = x0 + 1;
            float vy0 = (y0 >= 0 && y0 < HH) ? 1.f : 0.f;
            float vy1 = (y1 >= 0 && y1 < HH) ? 1.f : 0.f;
            float vx0 = (x0 >= 0 && x0 < WW) ? 1.f : 0.f;
            float vx1 = (x1 >= 0 && x1 < WW) ? 1.f : 0.f;
            float w00 = wy0*wx0*vy0*vx0*m;
            float w01 = wy0*wx1*vy0*vx1*m;
            float w10 = wy1*wx0*vy1*vx0*m;
            float w11 = wy1*wx1*vy1*vx1*m;
            int y0c = min(max(y0, 0), HH-1), y1c = min(max(y1, 0), HH-1);
            int x0c = min(max(x0, 0), WW-1), x1c = min(max(x1, 0), WW-1);
            int o00 = y0c*WW + x0c, o01 = y0c*WW + x1c;
            int o10 = y1c*WW + x0c, o11 = y1c*WW + x1c;
            #pragma unroll 8
            for (int ci = 0; ci < 32; ci++) {
                const float* xc = xb + ci*HWsz;
                vals_s[(half*32 + ci)*WW + p] =
                    xc[o00]*w00 + xc[o01]*w01 + xc[o10]*w10 + xc[o11]*w11;
            }
        }
        // ---- stage this tap's weights: 64*64 floats = 1024 float4
        {
            const float4* wsrc = (const float4*)(g_wt + k*CC*OO);
            float4* wdst = (float4*)w_s;
            #pragma unroll
            for (int r = 0; r < 4; r++) wdst[t + 256*r] = wsrc[t + 256*r];
        }
        __syncthreads();
        // ---- accumulate: 4px x 4 oc-pairs packed register tile
        #pragma unroll 4
        for (int c = 0; c < CC; c++) {
            u64 v0 = pk2(vals_s[c*WW + pp],      vals_s[c*WW + pp]);
            u64 v1 = pk2(vals_s[c*WW + pp + 32], vals_s[c*WW + pp + 32]);
            u64 v2 = pk2(vals_s[c*WW + pp + 64], vals_s[c*WW + pp + 64]);
            u64 v3 = pk2(vals_s[c*WW + pp + 96], vals_s[c*WW + pp + 96]);
            const u64* wp = (const u64*)(w_s + c*OO + og*8);
            u64 w0 = wp[0], w1 = wp[1], w2 = wp[2], w3 = wp[3];
            ffma2(acc[0][0], v0, w0); ffma2(acc[0][1], v0, w1);
            ffma2(acc[0][2], v0, w2); ffma2(acc[0][3], v0, w3);
            ffma2(acc[1][0], v1, w0); ffma2(acc[1][1], v1, w1);
            ffma2(acc[1][2], v1, w2); ffma2(acc[1][3], v1, w3);
            ffma2(acc[2][0], v2, w0); ffma2(acc[2][1], v2, w1);
            ffma2(acc[2][2], v2, w2); ffma2(acc[2][3], v2, w3);
            ffma2(acc[3][0], v3, w0); ffma2(acc[3][1], v3, w1);
            ffma2(acc[3][2], v3, w2); ffma2(acc[3][3], v3, w3);
        }
        __syncthreads();
    }
    // ---- epilogue: add bias, write out (fully covers the poisoned buffer)
    #pragma unroll
    for (int op = 0; op < 4; op++) {
        int o0 = og*8 + op*2;
        float bv0 = bias[o0];
        float bv1 = bias[o0 + 1];
        float* ob0 = out + (size_t)((b*OO + o0    )*HH + y) * WW;
        float* ob1 = out + (size_t)((b*OO + o0 + 1)*HH + y) * WW;
        #pragma unroll
        for (int j = 0; j < 4; j++) {
            float2 a = upk2(acc[j][op]);
            ob0[pp + 32*j] = a.x + bv0;
            ob1[pp + 32*j] = a.y + bv1;
        }
    }
}

// ---------------------------------------------------------------------------
extern "C" void kernel_launch(void* const* d_in, const int* in_sizes, int n_in,
                              void* d_out, int out_size) {
    const float* x      = (const float*)d_in[0];  // (4,64,128,128)
    const float* w_om   = (const float*)d_in[1];  // (27,64,3,3)
    const float* b_om   = (const float*)d_in[2];  // (27,)
    const float* weight = (const float*)d_in[3];  // (64,64,3,3)
    const float* bias   = (const float*)d_in[4];  // (64,)
    float* out = (float*)d_out;                   // (4,64,128,128)

    (void)in_sizes; (void)n_in; (void)out_size;

    static const int smem_bytes = (CC*WW + CC*OO + 3*K2V*WW) * (int)sizeof(float); // 62976
    cudaFuncSetAttribute(deform_conv, cudaFuncAttributeMaxDynamicSharedMemorySize, smem_bytes);

    prep_weights<<<(K2V*CC*OO + 255)/256, 256>>>(weight, w_om);
    offset_conv<<<BB*HH, 256>>>(x, b_om);
    deform_conv<<<BB*HH, 256, smem_bytes>>>(x, bias, out);
}